// round 17
// baseline (speedup 1.0000x reference)
#include <cuda_runtime.h>
#include <cuda_bf16.h>
#include <cuda_fp16.h>
#include <cstdint>

#define N_NODES 100000
#define N_EDGES 1600000

// ---------------- scratch (device globals; no allocations) ----------------
__device__ int    g_cnt[N_NODES];                 // degree histogram
__device__ int    g_total;                        // running segment allocator
__device__ int    g_rank[N_EDGES];                // per-edge rank within its dst
__device__ int    g_start[N_NODES];               // segment start per node
__device__ int    g_deg[N_NODES];                 // degree per node
__device__ int    g_col[N_EDGES];                 // CSR column (src) indices
__device__ __half g_t1h[(size_t)N_NODES * 64];    // x @ W1n   (fp16, gathered)
__device__ float  g_u1[(size_t)N_NODES * 64];     // x @ W1s   (fp32, sequential)
__device__ float  g_h [(size_t)N_NODES * 64];     // layer-1 output (relu)
__device__ __half g_t2h[(size_t)N_NODES * 32];    // h @ W2n   (fp16, gathered)
__device__ float  g_u2[(size_t)N_NODES * 32];     // h @ W2s   (fp32, sequential)

__device__ __forceinline__ int detect_is64(const int* ei32) {
    return (ei32[1] == 0 && ei32[3] == 0 && ei32[5] == 0 && ei32[7] == 0) ? 1 : 0;
}

__device__ __forceinline__ unsigned f2tf32(float f) {
    unsigned r;
    asm("cvt.rna.tf32.f32 %0, %1;" : "=r"(r) : "f"(f));
    return r;
}
// accumulate 8 halves (one uint4) into 8 float accumulators
__device__ __forceinline__ void acc_h8(float* acc, uint4 v) {
    float2 a = __half22float2(*reinterpret_cast<__half2*>(&v.x));
    float2 b = __half22float2(*reinterpret_cast<__half2*>(&v.y));
    float2 c = __half22float2(*reinterpret_cast<__half2*>(&v.z));
    float2 d = __half22float2(*reinterpret_cast<__half2*>(&v.w));
    acc[0] += a.x; acc[1] += a.y; acc[2] += b.x; acc[3] += b.y;
    acc[4] += c.x; acc[5] += c.y; acc[6] += d.x; acc[7] += d.y;
}

// ---------------- CSR build (3 kernels, 8 edges/thread) ----------------
__global__ void count_kernel(const void* __restrict__ ei, int E) {
    int t = blockIdx.x * blockDim.x + threadIdx.x;
    if (t == 0) g_total = 0;
    int e0 = t * 8;
    if (e0 >= E) return;
    int is64 = detect_is64((const int*)ei);
    int m = E - e0; if (m > 8) m = 8;
    int d[8];
    if (is64) {
        const long long* p = (const long long*)ei + E;
        #pragma unroll
        for (int i = 0; i < 8; i++) if (i < m) d[i] = (int)p[e0 + i];
    } else {
        const int* p = (const int*)ei + E;
        #pragma unroll
        for (int i = 0; i < 8; i++) if (i < m) d[i] = p[e0 + i];
    }
    int r[8];
    #pragma unroll
    for (int i = 0; i < 8; i++) if (i < m) r[i] = atomicAdd(&g_cnt[d[i]], 1);
    #pragma unroll
    for (int i = 0; i < 8; i++) if (i < m) g_rank[e0 + i] = r[i];
}

__global__ void offs_kernel() {
    int tid = threadIdx.x;
    int n = blockIdx.x * 256 + tid;
    int lane = tid & 31, wid = tid >> 5;
    int c = (n < N_NODES) ? g_cnt[n] : 0;

    int v = c;
    #pragma unroll
    for (int off = 1; off < 32; off <<= 1) {
        int t = __shfl_up_sync(0xffffffffu, v, off);
        if (lane >= off) v += t;
    }
    int excl = v - c;

    __shared__ int woff[8];
    __shared__ int bbase;
    if (lane == 31) woff[wid] = v;
    __syncthreads();
    if (wid == 0) {
        int orig = (lane < 8) ? woff[lane] : 0;
        int wv = orig;
        #pragma unroll
        for (int off = 1; off < 8; off <<= 1) {
            int t = __shfl_up_sync(0xffffffffu, wv, off);
            if (lane >= off) wv += t;
        }
        if (lane == 7) bbase = atomicAdd(&g_total, wv);
        if (lane < 8) woff[lane] = wv - orig;
    }
    __syncthreads();

    if (n < N_NODES) {
        g_start[n] = bbase + woff[wid] + excl;
        g_deg[n]   = c;
        g_cnt[n]   = 0;
    }
}

__global__ void fill_kernel(const void* __restrict__ ei, int E) {
    int t = blockIdx.x * blockDim.x + threadIdx.x;
    int e0 = t * 8;
    if (e0 >= E) return;
    int is64 = detect_is64((const int*)ei);
    int m = E - e0; if (m > 8) m = 8;
    int s[8], d[8];
    if (is64) {
        const long long* p = (const long long*)ei;
        #pragma unroll
        for (int i = 0; i < 8; i++) if (i < m) { s[i] = (int)p[e0 + i]; d[i] = (int)p[E + e0 + i]; }
    } else {
        const int* p = (const int*)ei;
        #pragma unroll
        for (int i = 0; i < 8; i++) if (i < m) { s[i] = p[e0 + i]; d[i] = p[E + e0 + i]; }
    }
    int rk[8], st[8];
    #pragma unroll
    for (int i = 0; i < 8; i++) if (i < m) rk[i] = g_rank[e0 + i];
    #pragma unroll
    for (int i = 0; i < 8; i++) if (i < m) st[i] = g_start[d[i]];
    #pragma unroll
    for (int i = 0; i < 8; i++) if (i < m) g_col[st[i] + rk[i]] = s[i];
}

// ---------------- tf32 tensor-core MMA macro ----------------
#define MMA_TF32(c, a, b0_, b1_) \
    asm volatile("mma.sync.aligned.m16n8k8.row.col.f32.tf32.tf32.f32 " \
        "{%0,%1,%2,%3}, {%4,%5,%6,%7}, {%8,%9}, {%0,%1,%2,%3};" \
        : "+f"((c)[0]), "+f"((c)[1]), "+f"((c)[2]), "+f"((c)[3]) \
        : "r"((a)[0]), "r"((a)[1]), "r"((a)[2]), "r"((a)[3]), \
          "r"(b0_), "r"(b1_))

// ---------------- layer-1 GEMM via tf32 tensor cores ----------------
// [t1|u1] = x @ [W1n|W1s]: M=128 nodes/block, N=128 outs, K=64 (2 chunks).
// Chunk-1 features prefetched into registers during chunk-0 MMA.
__global__ __launch_bounds__(256, 2)
void gemmA_kernel(const float* __restrict__ src,
                  const float* __restrict__ Wa,   // [64, 64] = W1n
                  const float* __restrict__ Wb) { // [64, 64] = W1s
    constexpr int PX = 36;
    constexpr int PW = 136;
    __shared__ unsigned sX[128 * PX];
    __shared__ unsigned sW[32 * PW];

    int tid  = threadIdx.x;
    int base = blockIdx.x * 128;
    int w    = tid >> 5;
    int lane = tid & 31;
    int wm   = w & 3;
    int wn   = w >> 2;
    int gid  = lane >> 2;
    int ctid = lane & 3;

    int k4 = tid & 7;
    int r_[4], nc_[4];
    #pragma unroll
    for (int it = 0; it < 4; it++) {
        r_[it] = (tid + it * 256) >> 3;
        int n = base + r_[it];
        nc_[it] = (n < N_NODES) ? n : (N_NODES - 1);
    }

    float4 pf[4];
    auto load_x = [&](int c) {
        #pragma unroll
        for (int it = 0; it < 4; it++)
            pf[it] = *(const float4*)(src + (size_t)nc_[it] * 64 + c * 32 + k4 * 4);
    };
    auto store_x = [&]() {
        #pragma unroll
        for (int it = 0; it < 4; it++) {
            unsigned* d = sX + r_[it] * PX + k4 * 4;
            d[0] = f2tf32(pf[it].x); d[1] = f2tf32(pf[it].y);
            d[2] = f2tf32(pf[it].z); d[3] = f2tf32(pf[it].w);
        }
    };
    auto stage_w = [&](int c) {
        #pragma unroll
        for (int iw = 0; iw < 4; iw++) {
            int idx = tid + iw * 256;
            int kk = idx >> 5, jq = idx & 31;
            int k = c * 32 + kk;
            const float* wsrc = (jq < 16) ? (Wa + k * 64 + jq * 4)
                                          : (Wb + k * 64 + jq * 4 - 64);
            float4 v = *(const float4*)wsrc;
            unsigned* d = sW + kk * PW + jq * 4;
            d[0] = f2tf32(v.x); d[1] = f2tf32(v.y);
            d[2] = f2tf32(v.z); d[3] = f2tf32(v.w);
        }
    };

    float acc[2][8][4];
    #pragma unroll
    for (int mt = 0; mt < 2; mt++)
        #pragma unroll
        for (int nt = 0; nt < 8; nt++)
            #pragma unroll
            for (int i = 0; i < 4; i++) acc[mt][nt][i] = 0.0f;

    load_x(0);
    store_x();
    stage_w(0);
    __syncthreads();

    #pragma unroll 1
    for (int c = 0; c < 2; c++) {
        if (c < 1) load_x(1);             // chunk-1 LDGs in flight during MMA
        #pragma unroll
        for (int ks = 0; ks < 4; ks++) {
            int k0 = ks * 8;
            unsigned a[2][4];
            #pragma unroll
            for (int mt = 0; mt < 2; mt++) {
                int row = wm * 32 + mt * 16 + gid;
                a[mt][0] = sX[row * PX + k0 + ctid];
                a[mt][1] = sX[(row + 8) * PX + k0 + ctid];
                a[mt][2] = sX[row * PX + k0 + ctid + 4];
                a[mt][3] = sX[(row + 8) * PX + k0 + ctid + 4];
            }
            #pragma unroll
            for (int nt = 0; nt < 8; nt++) {
                int j = wn * 64 + nt * 8 + gid;
                unsigned b0 = sW[(k0 + ctid) * PW + j];
                unsigned b1 = sW[(k0 + ctid + 4) * PW + j];
                MMA_TF32(acc[0][nt], a[0], b0, b1);
                MMA_TF32(acc[1][nt], a[1], b0, b1);
            }
        }
        __syncthreads();
        if (c < 1) {
            store_x();
            stage_w(1);
            __syncthreads();
        }
    }

    #pragma unroll
    for (int mt = 0; mt < 2; mt++) {
        int n0 = base + wm * 32 + mt * 16 + gid;
        int n1 = n0 + 8;
        #pragma unroll
        for (int nt = 0; nt < 8; nt++) {
            int j = wn * 64 + nt * 8 + 2 * ctid;
            float* a = acc[mt][nt];
            if (n0 < N_NODES) {
                if (j < 64)
                    *(__half2*)(g_t1h + (size_t)n0 * 64 + j) = __floats2half2_rn(a[0], a[1]);
                else
                    *(float2*)(g_u1 + (size_t)n0 * 64 + (j - 64)) = make_float2(a[0], a[1]);
            }
            if (n1 < N_NODES) {
                if (j < 64)
                    *(__half2*)(g_t1h + (size_t)n1 * 64 + j) = __floats2half2_rn(a[2], a[3]);
                else
                    *(float2*)(g_u1 + (size_t)n1 * 64 + (j - 64)) = make_float2(a[2], a[3]);
            }
        }
    }
}

// ---------------- layer-2 GEMM via tf32 tensor cores ----------------
// [t2|u2] = h @ [W2n|W2s]: M=128 nodes/block, N=64 outs, K=64 (2 chunks).
__global__ __launch_bounds__(256, 2)
void gemmD_kernel(const float* __restrict__ Wa,   // [64, 32] = W2n
                  const float* __restrict__ Wb) { // [64, 32] = W2s
    constexpr int PX = 36;
    constexpr int PW = 72;
    const float* src = g_h;
    __shared__ unsigned sX[128 * PX];
    __shared__ unsigned sW[32 * PW];

    int tid  = threadIdx.x;
    int base = blockIdx.x * 128;
    int w    = tid >> 5;
    int lane = tid & 31;
    int wm   = w & 3;
    int wn   = w >> 2;
    int gid  = lane >> 2;
    int ctid = lane & 3;

    int k4 = tid & 7;
    int r_[4], nc_[4];
    #pragma unroll
    for (int it = 0; it < 4; it++) {
        r_[it] = (tid + it * 256) >> 3;
        int n = base + r_[it];
        nc_[it] = (n < N_NODES) ? n : (N_NODES - 1);
    }

    float4 pf[4];
    auto load_x = [&](int c) {
        #pragma unroll
        for (int it = 0; it < 4; it++)
            pf[it] = *(const float4*)(src + (size_t)nc_[it] * 64 + c * 32 + k4 * 4);
    };
    auto store_x = [&]() {
        #pragma unroll
        for (int it = 0; it < 4; it++) {
            unsigned* d = sX + r_[it] * PX + k4 * 4;
            d[0] = f2tf32(pf[it].x); d[1] = f2tf32(pf[it].y);
            d[2] = f2tf32(pf[it].z); d[3] = f2tf32(pf[it].w);
        }
    };
    auto stage_w = [&](int c) {
        #pragma unroll
        for (int iw = 0; iw < 2; iw++) {
            int idx = tid + iw * 256;
            int kk = idx >> 4, jq = idx & 15;
            int k = c * 32 + kk;
            const float* wsrc = (jq < 8) ? (Wa + k * 32 + jq * 4)
                                         : (Wb + k * 32 + (jq - 8) * 4);
            float4 v = *(const float4*)wsrc;
            unsigned* d = sW + kk * PW + jq * 4;
            d[0] = f2tf32(v.x); d[1] = f2tf32(v.y);
            d[2] = f2tf32(v.z); d[3] = f2tf32(v.w);
        }
    };

    float acc[2][4][4];
    #pragma unroll
    for (int mt = 0; mt < 2; mt++)
        #pragma unroll
        for (int nt = 0; nt < 4; nt++)
            #pragma unroll
            for (int i = 0; i < 4; i++) acc[mt][nt][i] = 0.0f;

    load_x(0);
    store_x();
    stage_w(0);
    __syncthreads();

    #pragma unroll 1
    for (int c = 0; c < 2; c++) {
        if (c < 1) load_x(1);
        #pragma unroll
        for (int ks = 0; ks < 4; ks++) {
            int k0 = ks * 8;
            unsigned a[2][4];
            #pragma unroll
            for (int mt = 0; mt < 2; mt++) {
                int row = wm * 32 + mt * 16 + gid;
                a[mt][0] = sX[row * PX + k0 + ctid];
                a[mt][1] = sX[(row + 8) * PX + k0 + ctid];
                a[mt][2] = sX[row * PX + k0 + ctid + 4];
                a[mt][3] = sX[(row + 8) * PX + k0 + ctid + 4];
            }
            #pragma unroll
            for (int nt = 0; nt < 4; nt++) {
                int j = wn * 32 + nt * 8 + gid;
                unsigned b0 = sW[(k0 + ctid) * PW + j];
                unsigned b1 = sW[(k0 + ctid + 4) * PW + j];
                MMA_TF32(acc[0][nt], a[0], b0, b1);
                MMA_TF32(acc[1][nt], a[1], b0, b1);
            }
        }
        __syncthreads();
        if (c < 1) {
            store_x();
            stage_w(1);
            __syncthreads();
        }
    }

    #pragma unroll
    for (int mt = 0; mt < 2; mt++) {
        int n0 = base + wm * 32 + mt * 16 + gid;
        int n1 = n0 + 8;
        #pragma unroll
        for (int nt = 0; nt < 4; nt++) {
            int j = wn * 32 + nt * 8 + 2 * ctid;
            float* a = acc[mt][nt];
            if (n0 < N_NODES) {
                if (j < 32)
                    *(__half2*)(g_t2h + (size_t)n0 * 32 + j) = __floats2half2_rn(a[0], a[1]);
                else
                    *(float2*)(g_u2 + (size_t)n0 * 32 + (j - 32)) = make_float2(a[0], a[1]);
            }
            if (n1 < N_NODES) {
                if (j < 32)
                    *(__half2*)(g_t2h + (size_t)n1 * 32 + j) = __floats2half2_rn(a[2], a[3]);
                else
                    *(float2*)(g_u2 + (size_t)n1 * 32 + (j - 32)) = make_float2(a[2], a[3]);
            }
        }
    }
}

// ---------------- gather-mean + epilogue kernels (fp16 uint4 gathers) ----------------
// layer 1: 8 lanes/node, 16B loads; h = relu(mean(t1)+u1+b1)
__global__ __launch_bounds__(256)
void aggH_kernel(const float* __restrict__ b1) {
    int tid = threadIdx.x;
    int g = tid >> 3;
    int c = tid & 7;
    int n = blockIdx.x * 32 + g;
    if (n >= N_NODES) return;
    int start = g_start[n], deg = g_deg[n], end = start + deg;
    float acc[8] = {0.f, 0.f, 0.f, 0.f, 0.f, 0.f, 0.f, 0.f};
    int i = start;
    for (; i + 3 < end; i += 4) {
        int s0 = g_col[i], s1 = g_col[i + 1], s2 = g_col[i + 2], s3 = g_col[i + 3];
        uint4 v0 = *(const uint4*)(g_t1h + (size_t)s0 * 64 + c * 8);
        uint4 v1 = *(const uint4*)(g_t1h + (size_t)s1 * 64 + c * 8);
        uint4 v2 = *(const uint4*)(g_t1h + (size_t)s2 * 64 + c * 8);
        uint4 v3 = *(const uint4*)(g_t1h + (size_t)s3 * 64 + c * 8);
        acc_h8(acc, v0); acc_h8(acc, v1); acc_h8(acc, v2); acc_h8(acc, v3);
    }
    for (; i < end; i++) {
        int s0 = g_col[i];
        uint4 v0 = *(const uint4*)(g_t1h + (size_t)s0 * 64 + c * 8);
        acc_h8(acc, v0);
    }
    float inv = 1.0f / fmaxf((float)deg, 1.0f);
    float4 ua = *(const float4*)(g_u1 + (size_t)n * 64 + c * 8);
    float4 ub = *(const float4*)(g_u1 + (size_t)n * 64 + c * 8 + 4);
    float4 ba = *(const float4*)(b1 + c * 8);
    float4 bbv = *(const float4*)(b1 + c * 8 + 4);
    float4 oa, ob;
    oa.x = fmaxf(fmaf(acc[0], inv, ua.x + ba.x), 0.0f);
    oa.y = fmaxf(fmaf(acc[1], inv, ua.y + ba.y), 0.0f);
    oa.z = fmaxf(fmaf(acc[2], inv, ua.z + ba.z), 0.0f);
    oa.w = fmaxf(fmaf(acc[3], inv, ua.w + ba.w), 0.0f);
    ob.x = fmaxf(fmaf(acc[4], inv, ub.x + bbv.x), 0.0f);
    ob.y = fmaxf(fmaf(acc[5], inv, ub.y + bbv.y), 0.0f);
    ob.z = fmaxf(fmaf(acc[6], inv, ub.z + bbv.z), 0.0f);
    ob.w = fmaxf(fmaf(acc[7], inv, ub.w + bbv.w), 0.0f);
    *(float4*)(g_h + (size_t)n * 64 + c * 8)     = oa;
    *(float4*)(g_h + (size_t)n * 64 + c * 8 + 4) = ob;
}

// layer 2: 4 lanes/node, 16B loads; out = mean(t2)+u2+b2
__global__ __launch_bounds__(256)
void agg_final_kernel(const float* __restrict__ b2, float* __restrict__ out) {
    int tid = threadIdx.x;
    int g = tid >> 2;
    int c = tid & 3;
    int n = blockIdx.x * 64 + g;
    if (n >= N_NODES) return;
    int start = g_start[n], deg = g_deg[n], end = start + deg;
    float acc[8] = {0.f, 0.f, 0.f, 0.f, 0.f, 0.f, 0.f, 0.f};
    int i = start;
    for (; i + 3 < end; i += 4) {
        int s0 = g_col[i], s1 = g_col[i + 1], s2 = g_col[i + 2], s3 = g_col[i + 3];
        uint4 v0 = *(const uint4*)(g_t2h + (size_t)s0 * 32 + c * 8);
        uint4 v1 = *(const uint4*)(g_t2h + (size_t)s1 * 32 + c * 8);
        uint4 v2 = *(const uint4*)(g_t2h + (size_t)s2 * 32 + c * 8);
        uint4 v3 = *(const uint4*)(g_t2h + (size_t)s3 * 32 + c * 8);
        acc_h8(acc, v0); acc_h8(acc, v1); acc_h8(acc, v2); acc_h8(acc, v3);
    }
    for (; i < end; i++) {
        int s0 = g_col[i];
        uint4 v0 = *(const uint4*)(g_t2h + (size_t)s0 * 32 + c * 8);
        acc_h8(acc, v0);
    }
    float inv = 1.0f / fmaxf((float)deg, 1.0f);
    float4 ua = *(const float4*)(g_u2 + (size_t)n * 32 + c * 8);
    float4 ub = *(const float4*)(g_u2 + (size_t)n * 32 + c * 8 + 4);
    float4 ba = *(const float4*)(b2 + c * 8);
    float4 bbv = *(const float4*)(b2 + c * 8 + 4);
    float4 oa, ob;
    oa.x = fmaf(acc[0], inv, ua.x + ba.x);
    oa.y = fmaf(acc[1], inv, ua.y + ba.y);
    oa.z = fmaf(acc[2], inv, ua.z + ba.z);
    oa.w = fmaf(acc[3], inv, ua.w + ba.w);
    ob.x = fmaf(acc[4], inv, ub.x + bbv.x);
    ob.y = fmaf(acc[5], inv, ub.y + bbv.y);
    ob.z = fmaf(acc[6], inv, ub.z + bbv.z);
    ob.w = fmaf(acc[7], inv, ub.w + bbv.w);
    *(float4*)(out + (size_t)n * 32 + c * 8)     = oa;
    *(float4*)(out + (size_t)n * 32 + c * 8 + 4) = ob;
}

// ---------------- launch ----------------
extern "C" void kernel_launch(void* const* d_in, const int* in_sizes, int n_in,
                              void* d_out, int out_size) {
    const float* x   = (const float*)d_in[0];
    const void*  ei  = d_in[1];
    const float* W1n = (const float*)d_in[2];
    const float* W1s = (const float*)d_in[3];
    const float* b1  = (const float*)d_in[4];
    const float* W2n = (const float*)d_in[5];
    const float* W2s = (const float*)d_in[6];
    const float* b2  = (const float*)d_in[7];
    float* out = (float*)d_out;
    int E = in_sizes[1] / 2;

    cudaStream_t s2;
    cudaStreamCreate(&s2);
    cudaEvent_t evFork, evJoin;
    cudaEventCreateWithFlags(&evFork, cudaEventDisableTiming);
    cudaEventCreateWithFlags(&evJoin, cudaEventDisableTiming);

    cudaEventRecord(evFork, 0);
    cudaStreamWaitEvent(s2, evFork, 0);

    // CSR build on side stream (8 edges/thread)
    count_kernel<<<(E / 8 + 256) / 256, 256, 0, s2>>>(ei, E);
    offs_kernel<<<(N_NODES + 255) / 256, 256, 0, s2>>>();
    fill_kernel<<<(E / 8 + 256) / 256, 256, 0, s2>>>(ei, E);
    cudaEventRecord(evJoin, s2);

    // layer-1 GEMM (tensor cores) on main stream, concurrent with CSR build
    gemmA_kernel<<<(N_NODES + 127) / 128, 256>>>(x, W1n, W1s);

    cudaStreamWaitEvent(0, evJoin, 0);

    aggH_kernel<<<(N_NODES + 31) / 32, 256>>>(b1);
    gemmD_kernel<<<(N_NODES + 127) / 128, 256>>>(W2n, W2s);
    agg_final_kernel<<<(N_NODES + 63) / 64, 256>>>(b2, out);

    cudaEventDestroy(evFork);
    cudaEventDestroy(evJoin);
    cudaStreamDestroy(s2);
}